// round 14
// baseline (speedup 1.0000x reference)
#include <cuda_runtime.h>
#include <cuda_fp16.h>
#include <cstdint>

#define WS    14
#define NTOK  196
#define DIM   768
#define NH    12
#define HD    64
#define BATCH 256
#define M1    (BATCH * NTOK)   // 50176
#define QKVC  (3 * DIM)        // 2304
#define K_TOT 768

// ---------------- scratch (static device arrays; no runtime alloc) ----------
__device__ __half g_qkv[(size_t)M1 * QKVC];   // fp16 qkv (q pre-scaled)
__device__ __half g_x16[(size_t)M1 * DIM];
__device__ __half g_a16[(size_t)M1 * DIM];
__device__ __half g_wq[(size_t)QKVC * DIM];
__device__ __half g_pw[(size_t)DIM * DIM];

// ---------------- PTX helpers (base-target features only) --------------------
__device__ __forceinline__ uint32_t smem_u32(const void* p) {
    uint32_t a;
    asm("{ .reg .u64 t; cvta.to.shared.u64 t, %1; cvt.u32.u64 %0, t; }" : "=r"(a) : "l"(p));
    return a;
}
#define CP_ASYNC16(sa, ga) \
    asm volatile("cp.async.cg.shared.global [%0], [%1], 16;" :: "r"(sa), "l"(ga))
#define CP_COMMIT() asm volatile("cp.async.commit_group;" ::: "memory")
#define CP_WAIT0()  asm volatile("cp.async.wait_group 0;"  ::: "memory")

__device__ __forceinline__ void ldsm_x4(uint32_t& r0, uint32_t& r1, uint32_t& r2,
                                        uint32_t& r3, uint32_t addr) {
    asm volatile("ldmatrix.sync.aligned.m8n8.x4.shared.b16 {%0,%1,%2,%3}, [%4];"
                 : "=r"(r0), "=r"(r1), "=r"(r2), "=r"(r3) : "r"(addr));
}
__device__ __forceinline__ void mma16816(float* d, const uint32_t* a, const uint32_t* b) {
    asm volatile(
        "mma.sync.aligned.m16n8k16.row.col.f32.f16.f16.f32 "
        "{%0,%1,%2,%3}, {%4,%5,%6,%7}, {%8,%9}, {%0,%1,%2,%3};"
        : "+f"(d[0]), "+f"(d[1]), "+f"(d[2]), "+f"(d[3])
        : "r"(a[0]), "r"(a[1]), "r"(a[2]), "r"(a[3]), "r"(b[0]), "r"(b[1]));
}

__device__ __forceinline__ uint32_t h2_bits(__half2 h) {
    union { __half2 h; uint32_t u; } cvt;
    cvt.h = h;
    return cvt.u;
}

// ---------------- fp32 -> fp16 convert (optional head-scale on first n elems) -
__global__ __launch_bounds__(256) void cvt_kernel(
    const float* __restrict__ in, __half* __restrict__ out, int n4,
    int scale_elems)   // elements [0, scale_elems) get *0.125 (exact)
{
    int i = blockIdx.x * blockDim.x + threadIdx.x;
    if (i >= n4) return;
    float4 v = ((const float4*)in)[i];
    if (i * 4 < scale_elems) {
        v.x *= 0.125f; v.y *= 0.125f; v.z *= 0.125f; v.w *= 0.125f;
    }
    uint2 o;
    o.x = h2_bits(__halves2half2(__float2half_rn(v.x), __float2half_rn(v.y)));
    o.y = h2_bits(__halves2half2(__float2half_rn(v.z), __float2half_rn(v.w)));
    ((uint2*)out)[i] = o;
}

// ---------------- fp16 mma.sync GEMM: 2-stage ring, 3 CTAs/SM -----------------
// C[M,N] = A[M,768] * W[N,768]^T (+bias), fp32 accumulate.
// 128x128 CTA tile, BK=64, 8 warps (warp tile 64x32), 2-stage cp.async ring,
// ONE __syncthreads per chunk (doubles as stage-overwrite fence).
#define BKEL   64
#define ROWB   144
#define TILEB  (128 * ROWB)            // 18432 B
#define STAGEB (2 * TILEB)             // A+W = 36864 B
#define NSTG   2
#define GSMEM  (NSTG * STAGEB)         // 73728 B -> 3 CTAs/SM
#define NCHUNK (K_TOT / BKEL)          // 12

template <bool HALF_OUT>
__global__ __launch_bounds__(256, 3) void gemm_fp16_mma(
    const __half* __restrict__ A, const __half* __restrict__ W,
    const float* __restrict__ bias, void* __restrict__ Cv, int ldc)
{
    extern __shared__ __align__(128) char smem[];
    const uint32_t s0 = smem_u32(smem);

    const int tid    = threadIdx.x;
    const int lane   = tid & 31;
    const int wid    = tid >> 5;
    const int warp_m = wid >> 2;       // 0..1
    const int warp_n = wid & 3;        // 0..3
    const int bm     = blockIdx.y * 128;
    const int bn     = blockIdx.x * 128;

    const int lrow0 = tid >> 3;          // 0..31
    const int lseg  = (tid & 7) * 16;

    auto load_chunk = [&](int c, int stage) {
        const int k0 = c * BKEL;
        const __half* gA = A + (size_t)bm * K_TOT + k0;
        const __half* gW = W + (size_t)bn * K_TOT + k0;
        const uint32_t dA = s0 + stage * STAGEB;
        const uint32_t dW = dA + TILEB;
        #pragma unroll
        for (int p = 0; p < 4; p++) {
            const int row = lrow0 + p * 32;
            const uint32_t so = row * ROWB + lseg;
            const size_t   go = (size_t)row * K_TOT;
            CP_ASYNC16(dA + so, (const char*)(gA + go) + lseg);
            CP_ASYNC16(dW + so, (const char*)(gW + go) + lseg);
        }
    };

    float acc[4][4][4];
    #pragma unroll
    for (int mi = 0; mi < 4; mi++)
        #pragma unroll
        for (int nj = 0; nj < 4; nj++)
            #pragma unroll
            for (int e = 0; e < 4; e++) acc[mi][nj][e] = 0.f;

    load_chunk(0, 0); CP_COMMIT();

    const uint32_t a_row  = warp_m * 64 + (lane & 15);
    const uint32_t a_coff = (lane >> 4) * 16;
    const uint32_t b_row  = warp_n * 32 + ((lane >> 4) << 3) + (lane & 7);
    const uint32_t b_coff = ((lane >> 3) & 1) * 16;

    #pragma unroll 1
    for (int c = 0; c < NCHUNK; c++) {
        CP_WAIT0();                     // chunk c's load complete
        __syncthreads();                // + all warps done computing chunk c-1
                                        //   (so overwriting stage (c+1)&1 below is safe)
        if (c + 1 < NCHUNK) { load_chunk(c + 1, (c + 1) & 1); CP_COMMIT(); }

        const uint32_t sA = s0 + (c & 1) * STAGEB;
        const uint32_t sW = sA + TILEB;

        #pragma unroll
        for (int kk = 0; kk < 4; kk++) {
            uint32_t b[4][2];
            #pragma unroll
            for (int nj2 = 0; nj2 < 2; nj2++) {
                uint32_t r0, r1, r2, r3;
                ldsm_x4(r0, r1, r2, r3,
                        sW + (b_row + nj2 * 16) * ROWB + kk * 32 + b_coff);
                b[nj2 * 2 + 0][0] = r0; b[nj2 * 2 + 0][1] = r1;
                b[nj2 * 2 + 1][0] = r2; b[nj2 * 2 + 1][1] = r3;
            }
            uint32_t a[4][4];
            #pragma unroll
            for (int mi = 0; mi < 4; mi++)
                ldsm_x4(a[mi][0], a[mi][1], a[mi][2], a[mi][3],
                        sA + (a_row + mi * 16) * ROWB + kk * 32 + a_coff);
            #pragma unroll
            for (int mi = 0; mi < 4; mi++)
                #pragma unroll
                for (int nj = 0; nj < 4; nj++)
                    mma16816(acc[mi][nj], a[mi], b[nj]);
        }
    }

    const int er = lane >> 2;
    const int ec = (lane & 3) * 2;
    #pragma unroll
    for (int mi = 0; mi < 4; mi++) {
        const int r0 = bm + warp_m * 64 + mi * 16 + er;
        #pragma unroll
        for (int nj = 0; nj < 4; nj++) {
            const int col = bn + warp_n * 32 + nj * 8 + ec;
            float2 v0 = make_float2(acc[mi][nj][0], acc[mi][nj][1]);
            float2 v1 = make_float2(acc[mi][nj][2], acc[mi][nj][3]);
            if (bias) {
                const float2 bv = *(const float2*)(bias + col);
                v0.x += bv.x; v0.y += bv.y;
                v1.x += bv.x; v1.y += bv.y;
            }
            if (HALF_OUT) {
                __half* C = (__half*)Cv;
                *(__half2*)(C + (size_t)r0 * ldc + col) =
                    __halves2half2(__float2half_rn(v0.x), __float2half_rn(v0.y));
                *(__half2*)(C + (size_t)(r0 + 8) * ldc + col) =
                    __halves2half2(__float2half_rn(v1.x), __float2half_rn(v1.y));
            } else {
                float* C = (float*)Cv;
                *(float2*)(C + (size_t)r0 * ldc + col)       = v0;
                *(float2*)(C + (size_t)(r0 + 8) * ldc + col) = v1;
            }
        }
    }
}

// ---------------- local attention v3: 8-lane-group parallel dots --------------
__global__ __launch_bounds__(NH * 32) void local_attn_kernel(
    const __half* __restrict__ Y, const float* __restrict__ rpb,
    __half* __restrict__ O)
{
    const int bq   = blockIdx.x;
    const int q    = bq % NTOK;
    const int qi   = q / WS, qj = q % WS;
    const int h    = threadIdx.x >> 5;
    const int lane = threadIdx.x & 31;
    const int g    = lane >> 3;          // group 0..3
    const int sl   = lane & 7;           // sub-lane 0..7

    const size_t qk_base = (size_t)bq * QKVC + h * HD;

    float qf[8];
    {
        uint4 qr = *(const uint4*)(Y + qk_base + sl * 8);
        const __half2* qh = (const __half2*)&qr;
        #pragma unroll
        for (int i = 0; i < 4; i++) {
            float2 f = __half22float2(qh[i]);
            qf[i * 2 + 0] = f.x; qf[i * 2 + 1] = f.y;
        }
    }

    float dots[3];
    #pragma unroll
    for (int r = 0; r < 3; r++) {
        const int t  = r * 4 + g;
        const int di = t / 3 - 1, dj = t - (t / 3) * 3 - 1;
        const int ki = qi + di, kj = qj + dj;
        const bool ok = (t < 9) && ((unsigned)ki < WS) && ((unsigned)kj < WS);
        const int noff = ok ? (di * WS + dj) : 0;
        uint4 kr = *(const uint4*)(Y + qk_base + (size_t)noff * QKVC + DIM + sl * 8);
        const __half2* kh = (const __half2*)&kr;
        float d = 0.f;
        #pragma unroll
        for (int i = 0; i < 4; i++) {
            float2 f = __half22float2(kh[i]);
            d = fmaf(qf[i * 2 + 0], f.x, d);
            d = fmaf(qf[i * 2 + 1], f.y, d);
        }
        d += __shfl_xor_sync(0xffffffffu, d, 4);
        d += __shfl_xor_sync(0xffffffffu, d, 2);
        d += __shfl_xor_sync(0xffffffffu, d, 1);
        if (ok) d += rpb[((13 - di) * 27 + (13 - dj)) * NH + h];
        dots[r] = ok ? d : -1e30f;
    }

    float logit[9];
    #pragma unroll
    for (int t = 0; t < 9; t++)
        logit[t] = __shfl_sync(0xffffffffu, dots[t >> 2], (t & 3) * 8);

    float m = logit[0];
    #pragma unroll
    for (int t = 1; t < 9; t++) m = fmaxf(m, logit[t]);

    float den = 0.f;
    float2 acc = make_float2(0.f, 0.f);
    #pragma unroll
    for (int t = 0; t < 9; t++) {
        const int di = t / 3 - 1, dj = t - (t / 3) * 3 - 1;
        const int ki = qi + di, kj = qj + dj;
        const bool ok = ((unsigned)ki < WS) && ((unsigned)kj < WS);
        const int noff = ok ? (di * WS + dj) : 0;
        float2 v2 = __half22float2(
            ((const __half2*)(Y + qk_base + (size_t)noff * QKVC + 2 * DIM))[lane]);
        float e = __expf(logit[t] - m);
        den  += e;
        acc.x = fmaf(e, v2.x, acc.x);
        acc.y = fmaf(e, v2.y, acc.y);
    }
    const float inv = 1.f / den;
    acc.x *= inv; acc.y *= inv;

    ((__half2*)(O + (size_t)bq * DIM + h * HD))[lane] =
        __halves2half2(__float2half_rn(acc.x), __float2half_rn(acc.y));
}

// ---------------------------------------------------------------------------
extern "C" void kernel_launch(void* const* d_in, const int* in_sizes, int n_in,
                              void* d_out, int out_size)
{
    const float* x      = (const float*)d_in[0];
    const float* w_qkv  = (const float*)d_in[1];
    const float* rpb    = (const float*)d_in[2];
    const float* proj_w = (const float*)d_in[3];
    const float* proj_b = (const float*)d_in[4];
    float* out = (float*)d_out;

    __half *qkv, *x16, *a16, *wq, *pw;
    cudaGetSymbolAddress((void**)&qkv, g_qkv);
    cudaGetSymbolAddress((void**)&x16, g_x16);
    cudaGetSymbolAddress((void**)&a16, g_a16);
    cudaGetSymbolAddress((void**)&wq,  g_wq);
    cudaGetSymbolAddress((void**)&pw,  g_pw);

    cudaFuncSetAttribute(gemm_fp16_mma<true>,
                         cudaFuncAttributeMaxDynamicSharedMemorySize, GSMEM);
    cudaFuncSetAttribute(gemm_fp16_mma<false>,
                         cudaFuncAttributeMaxDynamicSharedMemorySize, GSMEM);

    {
        int n4 = M1 * DIM / 4;
        cvt_kernel<<<(n4 + 255) / 256, 256>>>(x, x16, n4, 0);
    }
    {
        int n4 = QKVC * DIM / 4;
        // first 768x768 block of w_qkv is W_q: pre-scale by 0.125 (exact)
        cvt_kernel<<<(n4 + 255) / 256, 256>>>(w_qkv, wq, n4, DIM * DIM);
    }
    {
        int n4 = DIM * DIM / 4;
        cvt_kernel<<<(n4 + 255) / 256, 256>>>(proj_w, pw, n4, 0);
    }

    dim3 g1(QKVC / 128, M1 / 128);   // 18 x 392
    gemm_fp16_mma<true><<<g1, 256, GSMEM>>>(x16, wq, nullptr, qkv, QKVC);

    local_attn_kernel<<<M1, NH * 32>>>(qkv, rpb, a16);

    dim3 g3(DIM / 128, M1 / 128);    // 6 x 392
    gemm_fp16_mma<false><<<g3, 256, GSMEM>>>(a16, pw, proj_b, out, DIM);
}

// round 16
// speedup vs baseline: 1.4465x; 1.4465x over previous
#include <cuda_runtime.h>
#include <cuda_fp16.h>
#include <cstdint>

#define WS    14
#define NTOK  196
#define DIM   768
#define NH    12
#define HD    64
#define BATCH 256
#define M1    (BATCH * NTOK)   // 50176
#define QKVC  (3 * DIM)        // 2304
#define K_TOT 768

// ---------------- scratch (static device arrays; no runtime alloc) ----------
__device__ __half g_qkv[(size_t)M1 * QKVC];   // fp16 qkv (q pre-scaled)
__device__ __half g_x16[(size_t)M1 * DIM];
__device__ __half g_a16[(size_t)M1 * DIM];
__device__ __half g_wq[(size_t)QKVC * DIM];
__device__ __half g_pw[(size_t)DIM * DIM];

// ---------------- PTX helpers (base-target features only) --------------------
__device__ __forceinline__ uint32_t smem_u32(const void* p) {
    uint32_t a;
    asm("{ .reg .u64 t; cvta.to.shared.u64 t, %1; cvt.u32.u64 %0, t; }" : "=r"(a) : "l"(p));
    return a;
}
#define CP_ASYNC16(sa, ga) \
    asm volatile("cp.async.cg.shared.global [%0], [%1], 16;" :: "r"(sa), "l"(ga))
#define CP_COMMIT() asm volatile("cp.async.commit_group;" ::: "memory")
#define CP_WAIT1()  asm volatile("cp.async.wait_group 1;"  ::: "memory")

__device__ __forceinline__ void ldsm_x4(uint32_t& r0, uint32_t& r1, uint32_t& r2,
                                        uint32_t& r3, uint32_t addr) {
    asm volatile("ldmatrix.sync.aligned.m8n8.x4.shared.b16 {%0,%1,%2,%3}, [%4];"
                 : "=r"(r0), "=r"(r1), "=r"(r2), "=r"(r3) : "r"(addr));
}
__device__ __forceinline__ void mma16816(float* d, const uint32_t* a, const uint32_t* b) {
    asm volatile(
        "mma.sync.aligned.m16n8k16.row.col.f32.f16.f16.f32 "
        "{%0,%1,%2,%3}, {%4,%5,%6,%7}, {%8,%9}, {%0,%1,%2,%3};"
        : "+f"(d[0]), "+f"(d[1]), "+f"(d[2]), "+f"(d[3])
        : "r"(a[0]), "r"(a[1]), "r"(a[2]), "r"(a[3]), "r"(b[0]), "r"(b[1]));
}

__device__ __forceinline__ uint32_t h2_bits(__half2 h) {
    union { __half2 h; uint32_t u; } cvt;
    cvt.h = h;
    return cvt.u;
}

// ---------------- fused fp32 -> fp16 convert (x | w_qkv | proj_w) ------------
// Region layout (in float4 units):
//   [0, N4X)              : x        -> g_x16               (no scale)
//   [N4X, N4X+N4W)        : w_qkv    -> g_wq   (first 768x768 block *0.125)
//   [N4X+N4W, +N4P)       : proj_w   -> g_pw                (no scale)
#define N4X (M1 * DIM / 4)
#define N4W (QKVC * DIM / 4)
#define N4P (DIM * DIM / 4)

__global__ __launch_bounds__(256) void cvt_all_kernel(
    const float* __restrict__ x, const float* __restrict__ wqkv,
    const float* __restrict__ pjw,
    __half* __restrict__ ox, __half* __restrict__ owq, __half* __restrict__ opw)
{
    int i = blockIdx.x * blockDim.x + threadIdx.x;
    const float* src;
    __half* dst;
    int  li;
    bool scale = false;
    if (i < N4X) {
        src = x; dst = ox; li = i;
    } else if (i < N4X + N4W) {
        src = wqkv; dst = owq; li = i - N4X;
        scale = (li * 4) < DIM * DIM;      // W_q rows: fold 0.125 (exact)
    } else if (i < N4X + N4W + N4P) {
        src = pjw; dst = opw; li = i - N4X - N4W;
    } else return;

    float4 v = ((const float4*)src)[li];
    if (scale) { v.x *= 0.125f; v.y *= 0.125f; v.z *= 0.125f; v.w *= 0.125f; }
    uint2 o;
    o.x = h2_bits(__halves2half2(__float2half_rn(v.x), __float2half_rn(v.y)));
    o.y = h2_bits(__halves2half2(__float2half_rn(v.z), __float2half_rn(v.w)));
    ((uint2*)dst)[li] = o;
}

// ---------------- fp16 mma.sync GEMM (R12 config, proven best) ----------------
#define BKEL   64
#define ROWB   144
#define TILEB  (128 * ROWB)            // 18432 B
#define STAGEB (2 * TILEB)             // A+W = 36864 B
#define NSTG   3
#define GSMEM  (NSTG * STAGEB)         // 110592 B
#define NCHUNK (K_TOT / BKEL)          // 12

template <bool HALF_OUT>
__global__ __launch_bounds__(256, 2) void gemm_fp16_mma(
    const __half* __restrict__ A, const __half* __restrict__ W,
    const float* __restrict__ bias, void* __restrict__ Cv, int ldc)
{
    extern __shared__ __align__(128) char smem[];
    const uint32_t s0 = smem_u32(smem);

    const int tid    = threadIdx.x;
    const int lane   = tid & 31;
    const int wid    = tid >> 5;
    const int warp_m = wid >> 2;       // 0..1
    const int warp_n = wid & 3;        // 0..3
    const int bm     = blockIdx.y * 128;
    const int bn     = blockIdx.x * 128;

    const int lrow0 = tid >> 3;          // 0..31
    const int lseg  = (tid & 7) * 16;

    auto load_chunk = [&](int c, int stage) {
        const int k0 = c * BKEL;
        const __half* gA = A + (size_t)bm * K_TOT + k0;
        const __half* gW = W + (size_t)bn * K_TOT + k0;
        const uint32_t dA = s0 + stage * STAGEB;
        const uint32_t dW = dA + TILEB;
        #pragma unroll
        for (int p = 0; p < 4; p++) {
            const int row = lrow0 + p * 32;
            const uint32_t so = row * ROWB + lseg;
            const size_t   go = (size_t)row * K_TOT;
            CP_ASYNC16(dA + so, (const char*)(gA + go) + lseg);
            CP_ASYNC16(dW + so, (const char*)(gW + go) + lseg);
        }
    };

    float acc[4][4][4];
    #pragma unroll
    for (int mi = 0; mi < 4; mi++)
        #pragma unroll
        for (int nj = 0; nj < 4; nj++)
            #pragma unroll
            for (int e = 0; e < 4; e++) acc[mi][nj][e] = 0.f;

    load_chunk(0, 0); CP_COMMIT();
    load_chunk(1, 1); CP_COMMIT();

    const uint32_t a_row  = warp_m * 64 + (lane & 15);
    const uint32_t a_coff = (lane >> 4) * 16;
    const uint32_t b_row  = warp_n * 32 + ((lane >> 4) << 3) + (lane & 7);
    const uint32_t b_coff = ((lane >> 3) & 1) * 16;

    #pragma unroll 1
    for (int c = 0; c < NCHUNK; c++) {
        CP_WAIT1();
        __syncthreads();
        if (c + 2 < NCHUNK) load_chunk(c + 2, (c + 2) % NSTG);
        CP_COMMIT();

        const int stage = c % NSTG;
        const uint32_t sA = s0 + stage * STAGEB;
        const uint32_t sW = sA + TILEB;

        #pragma unroll
        for (int kk = 0; kk < 4; kk++) {
            uint32_t b[4][2];
            #pragma unroll
            for (int nj2 = 0; nj2 < 2; nj2++) {
                uint32_t r0, r1, r2, r3;
                ldsm_x4(r0, r1, r2, r3,
                        sW + (b_row + nj2 * 16) * ROWB + kk * 32 + b_coff);
                b[nj2 * 2 + 0][0] = r0; b[nj2 * 2 + 0][1] = r1;
                b[nj2 * 2 + 1][0] = r2; b[nj2 * 2 + 1][1] = r3;
            }
            uint32_t a[4][4];
            #pragma unroll
            for (int mi = 0; mi < 4; mi++)
                ldsm_x4(a[mi][0], a[mi][1], a[mi][2], a[mi][3],
                        sA + (a_row + mi * 16) * ROWB + kk * 32 + a_coff);
            #pragma unroll
            for (int mi = 0; mi < 4; mi++)
                #pragma unroll
                for (int nj = 0; nj < 4; nj++)
                    mma16816(acc[mi][nj], a[mi], b[nj]);
        }
    }

    const int er = lane >> 2;
    const int ec = (lane & 3) * 2;
    #pragma unroll
    for (int mi = 0; mi < 4; mi++) {
        const int r0 = bm + warp_m * 64 + mi * 16 + er;
        #pragma unroll
        for (int nj = 0; nj < 4; nj++) {
            const int col = bn + warp_n * 32 + nj * 8 + ec;
            float2 v0 = make_float2(acc[mi][nj][0], acc[mi][nj][1]);
            float2 v1 = make_float2(acc[mi][nj][2], acc[mi][nj][3]);
            if (bias) {
                const float2 bv = *(const float2*)(bias + col);
                v0.x += bv.x; v0.y += bv.y;
                v1.x += bv.x; v1.y += bv.y;
            }
            if (HALF_OUT) {
                __half* C = (__half*)Cv;
                *(__half2*)(C + (size_t)r0 * ldc + col) =
                    __halves2half2(__float2half_rn(v0.x), __float2half_rn(v0.y));
                *(__half2*)(C + (size_t)(r0 + 8) * ldc + col) =
                    __halves2half2(__float2half_rn(v1.x), __float2half_rn(v1.y));
            } else {
                float* C = (float*)Cv;
                *(float2*)(C + (size_t)r0 * ldc + col)       = v0;
                *(float2*)(C + (size_t)(r0 + 8) * ldc + col) = v1;
            }
        }
    }
}

// ---------------- local attention v4: 2 tokens/block for L1 reuse -------------
// Block = 2 adjacent tokens x 12 heads = 24 warps (768 threads). Token pairs
// never cross a window row (row length 14 is even), so they share 6 of 9
// neighbors -> second token's K/V loads hit L1 (32cyc vs L2 234).
// Per-warp math identical to v3 (8-lane-group parallel dots, exact softmax).
__global__ __launch_bounds__(NH * 32 * 2) void local_attn_kernel(
    const __half* __restrict__ Y, const float* __restrict__ rpb,
    __half* __restrict__ O)
{
    const int wid  = threadIdx.x >> 5;
    const int bq   = blockIdx.x * 2 + (wid >= NH ? 1 : 0);
    const int h    = wid >= NH ? wid - NH : wid;
    const int q    = bq % NTOK;
    const int qi   = q / WS, qj = q % WS;
    const int lane = threadIdx.x & 31;
    const int g    = lane >> 3;          // group 0..3
    const int sl   = lane & 7;           // sub-lane 0..7

    const size_t qk_base = (size_t)bq * QKVC + h * HD;

    float qf[8];
    {
        uint4 qr = *(const uint4*)(Y + qk_base + sl * 8);
        const __half2* qh = (const __half2*)&qr;
        #pragma unroll
        for (int i = 0; i < 4; i++) {
            float2 f = __half22float2(qh[i]);
            qf[i * 2 + 0] = f.x; qf[i * 2 + 1] = f.y;
        }
    }

    float dots[3];
    #pragma unroll
    for (int r = 0; r < 3; r++) {
        const int t  = r * 4 + g;
        const int di = t / 3 - 1, dj = t - (t / 3) * 3 - 1;
        const int ki = qi + di, kj = qj + dj;
        const bool ok = (t < 9) && ((unsigned)ki < WS) && ((unsigned)kj < WS);
        const int noff = ok ? (di * WS + dj) : 0;
        uint4 kr = *(const uint4*)(Y + qk_base + (size_t)noff * QKVC + DIM + sl * 8);
        const __half2* kh = (const __half2*)&kr;
        float d = 0.f;
        #pragma unroll
        for (int i = 0; i < 4; i++) {
            float2 f = __half22float2(kh[i]);
            d = fmaf(qf[i * 2 + 0], f.x, d);
            d = fmaf(qf[i * 2 + 1], f.y, d);
        }
        d += __shfl_xor_sync(0xffffffffu, d, 4);
        d += __shfl_xor_sync(0xffffffffu, d, 2);
        d += __shfl_xor_sync(0xffffffffu, d, 1);
        if (ok) d += rpb[((13 - di) * 27 + (13 - dj)) * NH + h];
        dots[r] = ok ? d : -1e30f;
    }

    float logit[9];
    #pragma unroll
    for (int t = 0; t < 9; t++)
        logit[t] = __shfl_sync(0xffffffffu, dots[t >> 2], (t & 3) * 8);

    float m = logit[0];
    #pragma unroll
    for (int t = 1; t < 9; t++) m = fmaxf(m, logit[t]);

    float den = 0.f;
    float2 acc = make_float2(0.f, 0.f);
    #pragma unroll
    for (int t = 0; t < 9; t++) {
        const int di = t / 3 - 1, dj = t - (t / 3) * 3 - 1;
        const int ki = qi + di, kj = qj + dj;
        const bool ok = ((unsigned)ki < WS) && ((unsigned)kj < WS);
        const int noff = ok ? (di * WS + dj) : 0;
        float2 v2 = __half22float2(
            ((const __half2*)(Y + qk_base + (size_t)noff * QKVC + 2 * DIM))[lane]);
        float e = __expf(logit[t] - m);
        den  += e;
        acc.x = fmaf(e, v2.x, acc.x);
        acc.y = fmaf(e, v2.y, acc.y);
    }
    const float inv = 1.f / den;
    acc.x *= inv; acc.y *= inv;

    ((__half2*)(O + (size_t)bq * DIM + h * HD))[lane] =
        __halves2half2(__float2half_rn(acc.x), __float2half_rn(acc.y));
}

// ---------------------------------------------------------------------------
extern "C" void kernel_launch(void* const* d_in, const int* in_sizes, int n_in,
                              void* d_out, int out_size)
{
    const float* x      = (const float*)d_in[0];
    const float* w_qkv  = (const float*)d_in[1];
    const float* rpb    = (const float*)d_in[2];
    const float* proj_w = (const float*)d_in[3];
    const float* proj_b = (const float*)d_in[4];
    float* out = (float*)d_out;

    __half *qkv, *x16, *a16, *wq, *pw;
    cudaGetSymbolAddress((void**)&qkv, g_qkv);
    cudaGetSymbolAddress((void**)&x16, g_x16);
    cudaGetSymbolAddress((void**)&a16, g_a16);
    cudaGetSymbolAddress((void**)&wq,  g_wq);
    cudaGetSymbolAddress((void**)&pw,  g_pw);

    cudaFuncSetAttribute(gemm_fp16_mma<true>,
                         cudaFuncAttributeMaxDynamicSharedMemorySize, GSMEM);
    cudaFuncSetAttribute(gemm_fp16_mma<false>,
                         cudaFuncAttributeMaxDynamicSharedMemorySize, GSMEM);

    {
        const int n4 = N4X + N4W + N4P;
        cvt_all_kernel<<<(n4 + 255) / 256, 256>>>(x, w_qkv, proj_w, x16, wq, pw);
    }

    dim3 g1(QKVC / 128, M1 / 128);   // 18 x 392
    gemm_fp16_mma<true><<<g1, 256, GSMEM>>>(x16, wq, nullptr, qkv, QKVC);

    local_attn_kernel<<<M1 / 2, NH * 32 * 2>>>(qkv, rpb, a16);

    dim3 g3(DIM / 128, M1 / 128);    // 6 x 392
    gemm_fp16_mma<false><<<g3, 256, GSMEM>>>(a16, pw, proj_b, out, DIM);
}